// round 1
// baseline (speedup 1.0000x reference)
#include <cuda_runtime.h>
#include <cstdint>
#include <cstddef>

#define Bsz 256
#define Isz 1024
#define Hn  8
#define Dd  128
#define Pp  2048
#define HDd 1024
#define EPSf 1e-5f

// ---------------- scratch (device global, no allocations) ----------------
// layout (floats):
#define OFF_XN 0u
#define OFF_XT 262144u
#define OFF_RT 786432u
#define OFF_XC 1048576u
#define OFF_Q  1572864u
#define OFF_K  1835008u
#define OFF_V  2097152u
#define OFF_OL 2359296u
#define OFF_SK 2621440u
#define OFF_Z  2883584u
#define OFF_IT 3145728u
#define OFF_FT 3147776u
#define SCRATCH_FLOATS 3149824u
__device__ float g_scratch[SCRATCH_FLOATS];

// ---------------- helpers ----------------
__device__ __forceinline__ uint32_t f2tf32(float x) {
    uint32_t r;
    asm("cvt.rna.tf32.f32 %0, %1;" : "=r"(r) : "f"(x));
    return r;
}

__device__ __forceinline__ void mma_tf32(float c[4], const uint32_t a[4], const uint32_t b[2]) {
    asm volatile(
        "mma.sync.aligned.m16n8k8.row.col.f32.tf32.tf32.f32 "
        "{%0,%1,%2,%3},{%4,%5,%6,%7},{%8,%9},{%0,%1,%2,%3};"
        : "+f"(c[0]), "+f"(c[1]), "+f"(c[2]), "+f"(c[3])
        : "r"(a[0]), "r"(a[1]), "r"(a[2]), "r"(a[3]), "r"(b[0]), "r"(b[1]));
}

__device__ __forceinline__ float warp_sum(float v) {
    #pragma unroll
    for (int o = 16; o; o >>= 1) v += __shfl_xor_sync(0xffffffffu, v, o);
    return v;
}

// ---------------- LayerNorm over I=1024 ----------------
__global__ __launch_bounds__(256) void ln_kernel(
    const float* __restrict__ seq, const float* __restrict__ g,
    const float* __restrict__ bv, float* __restrict__ xn)
{
    __shared__ float red[16];
    int b = blockIdx.x, t = threadIdx.x;
    const float4* rowp = (const float4*)(seq + (size_t)b * Isz);
    float4 x = rowp[t];
    float s  = x.x + x.y + x.z + x.w;
    float s2 = x.x * x.x + x.y * x.y + x.z * x.z + x.w * x.w;
    s = warp_sum(s); s2 = warp_sum(s2);
    int lane = t & 31, w = t >> 5;
    if (lane == 0) { red[w] = s; red[8 + w] = s2; }
    __syncthreads();
    float su = 0.f, sq = 0.f;
    #pragma unroll
    for (int i = 0; i < 8; i++) { su += red[i]; sq += red[8 + i]; }
    float mu  = su * (1.f / 1024.f);
    float var = sq * (1.f / 1024.f) - mu * mu;
    float rs  = rsqrtf(var + EPSf);
    int c = t * 4;
    float4 o;
    o.x = (x.x - mu) * rs * g[c + 0] + bv[c + 0];
    o.y = (x.y - mu) * rs * g[c + 1] + bv[c + 1];
    o.z = (x.z - mu) * rs * g[c + 2] + bv[c + 2];
    o.w = (x.w - mu) * rs * g[c + 3] + bv[c + 3];
    ((float4*)(xn + (size_t)b * Isz))[t] = o;
}

// ---------------- causal conv (K=4 along feature axis) + SiLU ----------------
__global__ __launch_bounds__(256) void conv_kernel(
    const float* __restrict__ xt, const float* __restrict__ cw,
    const float* __restrict__ cb, float* __restrict__ xc)
{
    __shared__ float sr[Pp + 3];
    int b = blockIdx.x, t = threadIdx.x;
    for (int p = t; p < Pp; p += 256) sr[3 + p] = xt[(size_t)b * Pp + p];
    if (t < 3) sr[t] = 0.f;
    float w0 = cw[0], w1 = cw[1], w2 = cw[2], w3 = cw[3], cbv = cb[0];
    __syncthreads();
    for (int p = t; p < Pp; p += 256) {
        float a = cbv + w0 * sr[p] + w1 * sr[p + 1] + w2 * sr[p + 2] + w3 * sr[p + 3];
        xc[(size_t)b * Pp + p] = a / (1.f + expf(-a));
    }
}

// ---------------- tf32 tensor-core GEMM: Y[M,N] = alpha*(X@W^T + bias) + res ----------------
// M = 256 fixed. X: [M,Kd] row-major; W: [N,Kd] row-major. BM=BN=64, BK=16, 128 threads.
__global__ __launch_bounds__(128) void gemm_tf32(
    const float* __restrict__ X, const float* __restrict__ W,
    const float* __restrict__ bias, const float* __restrict__ res,
    float* __restrict__ Y, int N, int Kd, float alpha)
{
    __shared__ uint32_t As[64][20];
    __shared__ uint32_t Bs[64][20];
    int t  = threadIdx.x;
    int m0 = blockIdx.x * 64, n0 = blockIdx.y * 64;
    int lane = t & 31, wid = t >> 5;
    int wm = (wid & 1) * 32, wn = (wid >> 1) * 32;
    int grp = lane >> 2, qid = lane & 3;

    float acc[2][4][4];
    #pragma unroll
    for (int i = 0; i < 2; i++)
        #pragma unroll
        for (int j = 0; j < 4; j++)
            #pragma unroll
            for (int l = 0; l < 4; l++) acc[i][j][l] = 0.f;

    int lr = t >> 2;          // 0..31
    int lc = (t & 3) * 4;     // 0,4,8,12

    for (int kt = 0; kt < Kd; kt += 16) {
        #pragma unroll
        for (int hh = 0; hh < 2; hh++) {
            int r = lr + hh * 32;
            float4 xv = *(const float4*)(X + (size_t)(m0 + r) * Kd + kt + lc);
            As[r][lc + 0] = f2tf32(xv.x);
            As[r][lc + 1] = f2tf32(xv.y);
            As[r][lc + 2] = f2tf32(xv.z);
            As[r][lc + 3] = f2tf32(xv.w);
            int nr = n0 + r;
            float4 wv = make_float4(0.f, 0.f, 0.f, 0.f);
            if (nr < N) wv = *(const float4*)(W + (size_t)nr * Kd + kt + lc);
            Bs[r][lc + 0] = f2tf32(wv.x);
            Bs[r][lc + 1] = f2tf32(wv.y);
            Bs[r][lc + 2] = f2tf32(wv.z);
            Bs[r][lc + 3] = f2tf32(wv.w);
        }
        __syncthreads();
        #pragma unroll
        for (int ks = 0; ks < 2; ks++) {
            uint32_t a[2][4], bfr[4][2];
            #pragma unroll
            for (int tm = 0; tm < 2; tm++) {
                int r0 = wm + tm * 16 + grp;
                a[tm][0] = As[r0][ks * 8 + qid];
                a[tm][1] = As[r0 + 8][ks * 8 + qid];
                a[tm][2] = As[r0][ks * 8 + qid + 4];
                a[tm][3] = As[r0 + 8][ks * 8 + qid + 4];
            }
            #pragma unroll
            for (int tn = 0; tn < 4; tn++) {
                int nr = wn + tn * 8 + grp;
                bfr[tn][0] = Bs[nr][ks * 8 + qid];
                bfr[tn][1] = Bs[nr][ks * 8 + qid + 4];
            }
            #pragma unroll
            for (int tm = 0; tm < 2; tm++)
                #pragma unroll
                for (int tn = 0; tn < 4; tn++)
                    mma_tf32(acc[tm][tn], a[tm], bfr[tn]);
        }
        __syncthreads();
    }

    // epilogue
    #pragma unroll
    for (int tm = 0; tm < 2; tm++) {
        #pragma unroll
        for (int tn = 0; tn < 4; tn++) {
            int rbase = m0 + wm + tm * 16 + grp;
            int cbase = n0 + wn + tn * 8 + qid * 2;
            #pragma unroll
            for (int half = 0; half < 2; half++) {
                int row = rbase + half * 8;
                #pragma unroll
                for (int cc = 0; cc < 2; cc++) {
                    int col = cbase + cc;
                    if (col < N) {
                        float y = acc[tm][tn][half * 2 + cc];
                        y = alpha * (y + (bias ? bias[col] : 0.f));
                        if (res) y += res[(size_t)row * N + col];
                        Y[(size_t)row * N + col] = y;
                    }
                }
            }
        }
    }
}

// ---------------- fused state update + gating + groupnorm + skip ----------------
// one block per (b,h); 128 threads (4 warps, each warp owns 32 rows of the 128x128 tile)
__global__ __launch_bounds__(128) void gate_kernel(
    const float* __restrict__ c0, const float* __restrict__ n0,
    const float* __restrict__ m0, const float* __restrict__ gn_g,
    const float* __restrict__ gn_b,
    const float* __restrict__ q, const float* __restrict__ k,
    const float* __restrict__ v, const float* __restrict__ ol,
    const float* __restrict__ sk, const float* __restrict__ rt,
    const float* __restrict__ it, const float* __restrict__ ft,
    float* __restrict__ ct_out, float* __restrict__ n_out,
    float* __restrict__ m_out, float* __restrict__ z_out)
{
    __shared__ float qs[128], ks[128], vs[128], nums[128], red[8];
    int bh = blockIdx.x;
    int h  = bh & 7;
    int t = threadIdx.x, lane = t & 31, w = t >> 5;

    float itv = it[bh], ftv = ft[bh], m0v = m0[bh];
    float mt = fmaxf(ftv + m0v, itv);
    float ie = expf(itv - mt);
    float fe = expf(ftv - mt + m0v);
    if (t == 0) m_out[bh] = mt;

    int base = bh * Dd;   // == b*HD + h*D for [B,HD] arrays too
    float qv = q[base + t], kv = k[base + t], vv = v[base + t];
    qs[t] = qv; ks[t] = kv; vs[t] = vv;

    float ntv = fe * n0[base + t] + ie * kv;
    n_out[base + t] = ntv;

    float dpart = warp_sum(ntv * qv);
    if (lane == 0) red[w] = dpart;
    __syncthreads();
    float den = fmaxf(1.0f, red[0] + red[1] + red[2] + red[3]);

    float4 kk = ((const float4*)ks)[lane];
    float4 qq = ((const float4*)qs)[lane];
    size_t crow_base = (size_t)bh * (Dd * Dd);
    for (int d = w; d < Dd; d += 4) {
        float vd = vs[d];
        float4 c0v = ((const float4*)(c0 + crow_base + (size_t)d * Dd))[lane];
        float4 ctv;
        float ivd = ie * vd;
        ctv.x = fe * c0v.x + ivd * kk.x;
        ctv.y = fe * c0v.y + ivd * kk.y;
        ctv.z = fe * c0v.z + ivd * kk.z;
        ctv.w = fe * c0v.w + ivd * kk.w;
        ((float4*)(ct_out + crow_base + (size_t)d * Dd))[lane] = ctv;
        float p = ctv.x * qq.x + ctv.y * qq.y + ctv.z * qq.z + ctv.w * qq.w;
        p = warp_sum(p);
        if (lane == 0) nums[d] = p;
    }
    __syncthreads();

    float numd = nums[t];
    float olv = ol[base + t];
    float osig = 1.f / (1.f + expf(-olv));
    float hd = osig * numd / den;

    float s1 = warp_sum(hd);
    float s2 = warp_sum(hd * hd);
    if (lane == 0) { red[w] = s1; red[4 + w] = s2; }
    __syncthreads();
    float mu  = (red[0] + red[1] + red[2] + red[3]) * (1.f / 128.f);
    float msq = (red[4] + red[5] + red[6] + red[7]) * (1.f / 128.f);
    float var = msq - mu * mu;
    float hn = (hd - mu) * rsqrtf(var + EPSf);

    float val = hn * gn_g[h * Dd + t] + gn_b[h * Dd + t] + sk[base + t];
    float rv = rt[base + t];
    val *= rv / (1.f + expf(-rv));
    z_out[base + t] = val;
}

// ---------------- launch ----------------
extern "C" void kernel_launch(void* const* d_in, const int* in_sizes, int n_in,
                              void* d_out, int out_size)
{
    const float* seq    = (const float*)d_in[0];
    const float* c0     = (const float*)d_in[1];
    const float* n0     = (const float*)d_in[2];
    const float* m0     = (const float*)d_in[3];
    const float* ln_g   = (const float*)d_in[4];
    const float* ln_b   = (const float*)d_in[5];
    const float* gn_g   = (const float*)d_in[6];
    const float* gn_b   = (const float*)d_in[7];
    const float* W_upl  = (const float*)d_in[8];
    const float* b_upl  = (const float*)d_in[9];
    const float* W_upr  = (const float*)d_in[10];
    const float* b_upr  = (const float*)d_in[11];
    const float* W_down = (const float*)d_in[12];
    const float* b_down = (const float*)d_in[13];
    const float* conv_w = (const float*)d_in[14];
    const float* conv_b = (const float*)d_in[15];
    const float* W_skip = (const float*)d_in[16];
    const float* W_i    = (const float*)d_in[17];
    const float* b_i    = (const float*)d_in[18];
    const float* W_f    = (const float*)d_in[19];
    const float* b_f    = (const float*)d_in[20];
    const float* W_o    = (const float*)d_in[21];
    const float* b_o    = (const float*)d_in[22];
    const float* W_q    = (const float*)d_in[23];
    const float* b_q    = (const float*)d_in[24];
    const float* W_k    = (const float*)d_in[25];
    const float* b_k    = (const float*)d_in[26];
    const float* W_v    = (const float*)d_in[27];
    const float* b_v    = (const float*)d_in[28];

    void* sp = nullptr;
    cudaGetSymbolAddress(&sp, g_scratch);
    float* S  = (float*)sp;
    float* xn = S + OFF_XN;
    float* xt = S + OFF_XT;
    float* rt = S + OFF_RT;
    float* xc = S + OFF_XC;
    float* q  = S + OFF_Q;
    float* k  = S + OFF_K;
    float* v  = S + OFF_V;
    float* ol = S + OFF_OL;
    float* sk = S + OFF_SK;
    float* z  = S + OFF_Z;
    float* it = S + OFF_IT;
    float* ft = S + OFF_FT;

    float* outp = (float*)d_out;
    float* ct   = outp + (size_t)Bsz * Isz;
    float* nt   = ct + (size_t)Bsz * Hn * Dd * Dd;
    float* mt   = nt + (size_t)Bsz * Hn * Dd;

    const float kscale = 0.08838834764831845f;  // 1/sqrt(128)

    ln_kernel<<<Bsz, 256>>>(seq, ln_g, ln_b, xn);

    gemm_tf32<<<dim3(4, 32), 128>>>(xn, W_upl, b_upl, nullptr, xt, Pp,  Isz, 1.f);
    gemm_tf32<<<dim3(4, 16), 128>>>(xn, W_upr, b_upr, nullptr, rt, HDd, Isz, 1.f);

    conv_kernel<<<Bsz, 256>>>(xt, conv_w, conv_b, xc);

    gemm_tf32<<<dim3(4, 16), 128>>>(xc, W_q,    b_q,    nullptr, q,  HDd, Pp, 1.f);
    gemm_tf32<<<dim3(4, 16), 128>>>(xc, W_k,    b_k,    nullptr, k,  HDd, Pp, kscale);
    gemm_tf32<<<dim3(4, 16), 128>>>(xt, W_v,    b_v,    nullptr, v,  HDd, Pp, 1.f);
    gemm_tf32<<<dim3(4, 16), 128>>>(xt, W_o,    b_o,    nullptr, ol, HDd, Pp, 1.f);
    gemm_tf32<<<dim3(4, 16), 128>>>(xc, W_skip, nullptr, nullptr, sk, HDd, Pp, 1.f);
    gemm_tf32<<<dim3(4, 1),  128>>>(xc, W_i,    b_i,    nullptr, it, Hn,  Pp, 1.f);
    gemm_tf32<<<dim3(4, 1),  128>>>(xc, W_f,    b_f,    nullptr, ft, Hn,  Pp, 1.f);

    gate_kernel<<<Bsz * Hn, 128>>>(c0, n0, m0, gn_g, gn_b, q, k, v, ol, sk, rt,
                                   it, ft, ct, nt, mt, z);

    gemm_tf32<<<dim3(4, 16), 128>>>(z, W_down, b_down, seq, outp, Isz, HDd, 1.f);
}

// round 2
// speedup vs baseline: 4.5071x; 4.5071x over previous
#include <cuda_runtime.h>
#include <cstdint>
#include <cstddef>

#define Bsz 256
#define Isz 1024
#define Hn  8
#define Dd  128
#define Pp  2048
#define HDd 1024
#define EPSf 1e-5f

// ---------------- scratch (device global, no allocations) ----------------
#define OFF_XN 0u
#define OFF_XT 262144u
#define OFF_RT 786432u
#define OFF_XC 1048576u
#define OFF_Q  1572864u
#define OFF_K  1835008u
#define OFF_V  2097152u
#define OFF_OL 2359296u
#define OFF_SK 2621440u
#define OFF_Z  2883584u
#define OFF_IT 3145728u
#define OFF_FT 3147776u
#define SCRATCH_FLOATS 3149824u
__device__ float g_scratch[SCRATCH_FLOATS];

// ---------------- helpers ----------------
__device__ __forceinline__ uint32_t f2tf32(float x) {
    uint32_t r;
    asm("cvt.rna.tf32.f32 %0, %1;" : "=r"(r) : "f"(x));
    return r;
}

__device__ __forceinline__ void mma_tf32(float c[4], const uint32_t a[4], const uint32_t b[2]) {
    asm volatile(
        "mma.sync.aligned.m16n8k8.row.col.f32.tf32.tf32.f32 "
        "{%0,%1,%2,%3},{%4,%5,%6,%7},{%8,%9},{%0,%1,%2,%3};"
        : "+f"(c[0]), "+f"(c[1]), "+f"(c[2]), "+f"(c[3])
        : "r"(a[0]), "r"(a[1]), "r"(a[2]), "r"(a[3]), "r"(b[0]), "r"(b[1]));
}

__device__ __forceinline__ float warp_sum(float v) {
    #pragma unroll
    for (int o = 16; o; o >>= 1) v += __shfl_xor_sync(0xffffffffu, v, o);
    return v;
}

// ---------------- LayerNorm over I=1024 ----------------
__global__ __launch_bounds__(256) void ln_kernel(
    const float* __restrict__ seq, const float* __restrict__ g,
    const float* __restrict__ bv, float* __restrict__ xn)
{
    __shared__ float red[16];
    int b = blockIdx.x, t = threadIdx.x;
    const float4* rowp = (const float4*)(seq + (size_t)b * Isz);
    float4 x = rowp[t];
    float s  = x.x + x.y + x.z + x.w;
    float s2 = x.x * x.x + x.y * x.y + x.z * x.z + x.w * x.w;
    s = warp_sum(s); s2 = warp_sum(s2);
    int lane = t & 31, w = t >> 5;
    if (lane == 0) { red[w] = s; red[8 + w] = s2; }
    __syncthreads();
    float su = 0.f, sq = 0.f;
    #pragma unroll
    for (int i = 0; i < 8; i++) { su += red[i]; sq += red[8 + i]; }
    float mu  = su * (1.f / 1024.f);
    float var = sq * (1.f / 1024.f) - mu * mu;
    float rs  = rsqrtf(var + EPSf);
    int c = t * 4;
    float4 o;
    o.x = (x.x - mu) * rs * g[c + 0] + bv[c + 0];
    o.y = (x.y - mu) * rs * g[c + 1] + bv[c + 1];
    o.z = (x.z - mu) * rs * g[c + 2] + bv[c + 2];
    o.w = (x.w - mu) * rs * g[c + 3] + bv[c + 3];
    ((float4*)(xn + (size_t)b * Isz))[t] = o;
}

// ---------------- causal conv (K=4 along feature axis) + SiLU ----------------
__global__ __launch_bounds__(256) void conv_kernel(
    const float* __restrict__ xt, const float* __restrict__ cw,
    const float* __restrict__ cb, float* __restrict__ xc)
{
    __shared__ float sr[Pp + 3];
    int b = blockIdx.x, t = threadIdx.x;
    for (int p = t; p < Pp; p += 256) sr[3 + p] = xt[(size_t)b * Pp + p];
    if (t < 3) sr[t] = 0.f;
    float w0 = cw[0], w1 = cw[1], w2 = cw[2], w3 = cw[3], cbv = cb[0];
    __syncthreads();
    for (int p = t; p < Pp; p += 256) {
        float a = cbv + w0 * sr[p] + w1 * sr[p + 1] + w2 * sr[p + 2] + w3 * sr[p + 3];
        xc[(size_t)b * Pp + p] = a / (1.f + expf(-a));
    }
}

// ---------------- i/f gate projections (N=8 each) via warp dots ----------------
__global__ __launch_bounds__(256) void if_kernel(
    const float* __restrict__ xc,
    const float* __restrict__ Wi, const float* __restrict__ bi,
    const float* __restrict__ Wf, const float* __restrict__ bfv,
    float* __restrict__ it, float* __restrict__ ft)
{
    __shared__ float4 xs4[Pp / 4];
    int b = blockIdx.x, t = threadIdx.x;
    const float4* xrow = (const float4*)(xc + (size_t)b * Pp);
    for (int i = t; i < Pp / 4; i += 256) xs4[i] = xrow[i];
    __syncthreads();
    int wid = t >> 5, lane = t & 31;   // wid == head
    const float4* wi = (const float4*)(Wi + (size_t)wid * Pp);
    const float4* wf = (const float4*)(Wf + (size_t)wid * Pp);
    float si = 0.f, sf = 0.f;
    for (int i = lane; i < Pp / 4; i += 32) {
        float4 x = xs4[i];
        float4 a = wi[i], c = wf[i];
        si += x.x * a.x + x.y * a.y + x.z * a.z + x.w * a.w;
        sf += x.x * c.x + x.y * c.y + x.z * c.z + x.w * c.w;
    }
    si = warp_sum(si); sf = warp_sum(sf);
    if (lane == 0) {
        it[b * Hn + wid] = si + bi[wid];
        ft[b * Hn + wid] = sf + bfv[wid];
    }
}

// ---------------- batched tf32 GEMM: per-job Y = alpha*(X@W^T + bias) + res ----
// BM=128, BN=128, BK=16, 256 threads (8 warps, warp tile 64x32), double-buffered.
#define GBM 128
#define GBN 128
#define GBK 16

struct Jobs {
    const float* X[5];
    const float* W[5];
    const float* bias[5];
    const float* res[5];
    float* out[5];
    float alpha[5];
    int N[5];
    int nt_start[6];
    int K;
};

__device__ __forceinline__ void gemm_compute(
    const uint32_t (*As)[20], const uint32_t (*Bss)[20],
    float acc[4][4][4], int wm, int wn, int grp, int qid)
{
    #pragma unroll
    for (int ks = 0; ks < 2; ks++) {
        uint32_t a[4][4], bb[4][2];
        #pragma unroll
        for (int tm = 0; tm < 4; tm++) {
            int r = wm + tm * 16 + grp;
            a[tm][0] = As[r][ks * 8 + qid];
            a[tm][1] = As[r + 8][ks * 8 + qid];
            a[tm][2] = As[r][ks * 8 + qid + 4];
            a[tm][3] = As[r + 8][ks * 8 + qid + 4];
        }
        #pragma unroll
        for (int tn = 0; tn < 4; tn++) {
            int c = wn + tn * 8 + grp;
            bb[tn][0] = Bss[c][ks * 8 + qid];
            bb[tn][1] = Bss[c][ks * 8 + qid + 4];
        }
        #pragma unroll
        for (int tm = 0; tm < 4; tm++)
            #pragma unroll
            for (int tn = 0; tn < 4; tn++)
                mma_tf32(acc[tm][tn], a[tm], bb[tn]);
    }
}

__global__ __launch_bounds__(256, 2) void gemm_multi(Jobs J)
{
    __shared__ uint32_t As[2][GBM][20];
    __shared__ uint32_t Bs[2][GBN][20];

    int yt = blockIdx.y;
    int j = 0;
    while (yt >= J.nt_start[j + 1]) j++;
    const float* X = J.X[j];
    const float* W = J.W[j];
    int n0 = (yt - J.nt_start[j]) * GBN;
    int m0 = blockIdx.x * GBM;
    int K = J.K;

    int t = threadIdx.x, lane = t & 31, wid = t >> 5;
    int wm = (wid & 1) * 64, wn = (wid >> 1) * 32;
    int grp = lane >> 2, qid = lane & 3;

    float acc[4][4][4];
    #pragma unroll
    for (int i = 0; i < 4; i++)
        #pragma unroll
        for (int jj = 0; jj < 4; jj++)
            #pragma unroll
            for (int l = 0; l < 4; l++) acc[i][jj][l] = 0.f;

    float4 aR[2], bR[2];

    // prologue: load stage 0
    #pragma unroll
    for (int i = 0; i < 2; i++) {
        int idx = t + i * 256;
        int r = idx >> 2, c = (idx & 3) * 4;
        aR[i] = *(const float4*)(X + (size_t)(m0 + r) * K + c);
        bR[i] = *(const float4*)(W + (size_t)(n0 + r) * K + c);
    }
    #pragma unroll
    for (int i = 0; i < 2; i++) {
        int idx = t + i * 256;
        int r = idx >> 2, c = (idx & 3) * 4;
        As[0][r][c + 0] = f2tf32(aR[i].x);
        As[0][r][c + 1] = f2tf32(aR[i].y);
        As[0][r][c + 2] = f2tf32(aR[i].z);
        As[0][r][c + 3] = f2tf32(aR[i].w);
        Bs[0][r][c + 0] = f2tf32(bR[i].x);
        Bs[0][r][c + 1] = f2tf32(bR[i].y);
        Bs[0][r][c + 2] = f2tf32(bR[i].z);
        Bs[0][r][c + 3] = f2tf32(bR[i].w);
    }
    __syncthreads();

    int buf = 0;
    for (int kt = GBK; kt < K; kt += GBK) {
        // prefetch next stage (global) while computing current
        #pragma unroll
        for (int i = 0; i < 2; i++) {
            int idx = t + i * 256;
            int r = idx >> 2, c = (idx & 3) * 4;
            aR[i] = *(const float4*)(X + (size_t)(m0 + r) * K + kt + c);
            bR[i] = *(const float4*)(W + (size_t)(n0 + r) * K + kt + c);
        }
        gemm_compute(As[buf], Bs[buf], acc, wm, wn, grp, qid);
        #pragma unroll
        for (int i = 0; i < 2; i++) {
            int idx = t + i * 256;
            int r = idx >> 2, c = (idx & 3) * 4;
            As[buf ^ 1][r][c + 0] = f2tf32(aR[i].x);
            As[buf ^ 1][r][c + 1] = f2tf32(aR[i].y);
            As[buf ^ 1][r][c + 2] = f2tf32(aR[i].z);
            As[buf ^ 1][r][c + 3] = f2tf32(aR[i].w);
            Bs[buf ^ 1][r][c + 0] = f2tf32(bR[i].x);
            Bs[buf ^ 1][r][c + 1] = f2tf32(bR[i].y);
            Bs[buf ^ 1][r][c + 2] = f2tf32(bR[i].z);
            Bs[buf ^ 1][r][c + 3] = f2tf32(bR[i].w);
        }
        __syncthreads();
        buf ^= 1;
    }
    gemm_compute(As[buf], Bs[buf], acc, wm, wn, grp, qid);

    // epilogue
    const float* bias = J.bias[j];
    const float* res  = J.res[j];
    float* out        = J.out[j];
    float alpha       = J.alpha[j];
    int N             = J.N[j];

    #pragma unroll
    for (int tm = 0; tm < 4; tm++) {
        #pragma unroll
        for (int half = 0; half < 2; half++) {
            int row = m0 + wm + tm * 16 + grp + half * 8;
            #pragma unroll
            for (int tn = 0; tn < 4; tn++) {
                int col = n0 + wn + tn * 8 + qid * 2;
                float y0 = acc[tm][tn][half * 2 + 0];
                float y1 = acc[tm][tn][half * 2 + 1];
                if (bias) { y0 += bias[col]; y1 += bias[col + 1]; }
                y0 *= alpha; y1 *= alpha;
                if (res) {
                    y0 += res[(size_t)row * N + col];
                    y1 += res[(size_t)row * N + col + 1];
                }
                float2 yv; yv.x = y0; yv.y = y1;
                *(float2*)(out + (size_t)row * N + col) = yv;
            }
        }
    }
}

// ---------------- fused state update + gating + groupnorm + skip ----------------
__global__ __launch_bounds__(128) void gate_kernel(
    const float* __restrict__ c0, const float* __restrict__ n0,
    const float* __restrict__ m0, const float* __restrict__ gn_g,
    const float* __restrict__ gn_b,
    const float* __restrict__ q, const float* __restrict__ k,
    const float* __restrict__ v, const float* __restrict__ ol,
    const float* __restrict__ sk, const float* __restrict__ rt,
    const float* __restrict__ it, const float* __restrict__ ft,
    float* __restrict__ ct_out, float* __restrict__ n_out,
    float* __restrict__ m_out, float* __restrict__ z_out)
{
    __shared__ float qs[128], ks[128], vs[128], nums[128], red[8];
    int bh = blockIdx.x;
    int h  = bh & 7;
    int t = threadIdx.x, lane = t & 31, w = t >> 5;

    float itv = it[bh], ftv = ft[bh], m0v = m0[bh];
    float mt = fmaxf(ftv + m0v, itv);
    float ie = expf(itv - mt);
    float fe = expf(ftv - mt + m0v);
    if (t == 0) m_out[bh] = mt;

    int base = bh * Dd;
    float qv = q[base + t], kv = k[base + t], vv = v[base + t];
    qs[t] = qv; ks[t] = kv; vs[t] = vv;

    float ntv = fe * n0[base + t] + ie * kv;
    n_out[base + t] = ntv;

    float dpart = warp_sum(ntv * qv);
    if (lane == 0) red[w] = dpart;
    __syncthreads();
    float den = fmaxf(1.0f, red[0] + red[1] + red[2] + red[3]);

    float4 kk = ((const float4*)ks)[lane];
    float4 qq = ((const float4*)qs)[lane];
    size_t crow_base = (size_t)bh * (Dd * Dd);
    for (int d = w; d < Dd; d += 4) {
        float vd = vs[d];
        float4 c0v = ((const float4*)(c0 + crow_base + (size_t)d * Dd))[lane];
        float4 ctv;
        float ivd = ie * vd;
        ctv.x = fe * c0v.x + ivd * kk.x;
        ctv.y = fe * c0v.y + ivd * kk.y;
        ctv.z = fe * c0v.z + ivd * kk.z;
        ctv.w = fe * c0v.w + ivd * kk.w;
        ((float4*)(ct_out + crow_base + (size_t)d * Dd))[lane] = ctv;
        float p = ctv.x * qq.x + ctv.y * qq.y + ctv.z * qq.z + ctv.w * qq.w;
        p = warp_sum(p);
        if (lane == 0) nums[d] = p;
    }
    __syncthreads();

    float numd = nums[t];
    float olv = ol[base + t];
    float osig = 1.f / (1.f + expf(-olv));
    float hd = osig * numd / den;

    float s1 = warp_sum(hd);
    float s2 = warp_sum(hd * hd);
    if (lane == 0) { red[w] = s1; red[4 + w] = s2; }
    __syncthreads();
    float mu  = (red[0] + red[1] + red[2] + red[3]) * (1.f / 128.f);
    float msq = (red[4] + red[5] + red[6] + red[7]) * (1.f / 128.f);
    float var = msq - mu * mu;
    float hn = (hd - mu) * rsqrtf(var + EPSf);

    float val = hn * gn_g[h * Dd + t] + gn_b[h * Dd + t] + sk[base + t];
    float rv = rt[base + t];
    val *= rv / (1.f + expf(-rv));
    z_out[base + t] = val;
}

// ---------------- launch ----------------
extern "C" void kernel_launch(void* const* d_in, const int* in_sizes, int n_in,
                              void* d_out, int out_size)
{
    const float* seq    = (const float*)d_in[0];
    const float* c0     = (const float*)d_in[1];
    const float* n0     = (const float*)d_in[2];
    const float* m0     = (const float*)d_in[3];
    const float* ln_g   = (const float*)d_in[4];
    const float* ln_b   = (const float*)d_in[5];
    const float* gn_g   = (const float*)d_in[6];
    const float* gn_b   = (const float*)d_in[7];
    const float* W_upl  = (const float*)d_in[8];
    const float* b_upl  = (const float*)d_in[9];
    const float* W_upr  = (const float*)d_in[10];
    const float* b_upr  = (const float*)d_in[11];
    const float* W_down = (const float*)d_in[12];
    const float* b_down = (const float*)d_in[13];
    const float* conv_w = (const float*)d_in[14];
    const float* conv_b = (const float*)d_in[15];
    const float* W_skip = (const float*)d_in[16];
    const float* W_i    = (const float*)d_in[17];
    const float* b_i    = (const float*)d_in[18];
    const float* W_f    = (const float*)d_in[19];
    const float* b_f    = (const float*)d_in[20];
    const float* W_o    = (const float*)d_in[21];
    const float* b_o    = (const float*)d_in[22];
    const float* W_q    = (const float*)d_in[23];
    const float* b_q    = (const float*)d_in[24];
    const float* W_k    = (const float*)d_in[25];
    const float* b_k    = (const float*)d_in[26];
    const float* W_v    = (const float*)d_in[27];
    const float* b_v    = (const float*)d_in[28];

    void* sp = nullptr;
    cudaGetSymbolAddress(&sp, g_scratch);
    float* S  = (float*)sp;
    float* xn = S + OFF_XN;
    float* xt = S + OFF_XT;
    float* rt = S + OFF_RT;
    float* xc = S + OFF_XC;
    float* q  = S + OFF_Q;
    float* k  = S + OFF_K;
    float* v  = S + OFF_V;
    float* ol = S + OFF_OL;
    float* sk = S + OFF_SK;
    float* z  = S + OFF_Z;
    float* it = S + OFF_IT;
    float* ft = S + OFF_FT;

    float* outp = (float*)d_out;
    float* ct   = outp + (size_t)Bsz * Isz;
    float* nt   = ct + (size_t)Bsz * Hn * Dd * Dd;
    float* mt   = nt + (size_t)Bsz * Hn * Dd;

    const float kscale = 0.08838834764831845f;  // 1/sqrt(128)

    ln_kernel<<<Bsz, 256>>>(seq, ln_g, ln_b, xn);

    // up-projections: [upl N=2048][upr N=1024], K=1024 -> 24 n-tiles
    {
        Jobs J = {};
        J.K = Isz;
        J.X[0] = xn; J.W[0] = W_upl; J.bias[0] = b_upl; J.res[0] = nullptr;
        J.out[0] = xt; J.alpha[0] = 1.f; J.N[0] = Pp;
        J.X[1] = xn; J.W[1] = W_upr; J.bias[1] = b_upr; J.res[1] = nullptr;
        J.out[1] = rt; J.alpha[1] = 1.f; J.N[1] = HDd;
        J.nt_start[0] = 0; J.nt_start[1] = 16; J.nt_start[2] = 24;
        J.nt_start[3] = 24; J.nt_start[4] = 24; J.nt_start[5] = 24;
        gemm_multi<<<dim3(2, 24), 256>>>(J);
    }

    conv_kernel<<<Bsz, 256>>>(xt, conv_w, conv_b, xc);

    if_kernel<<<Bsz, 256>>>(xc, W_i, b_i, W_f, b_f, it, ft);

    // q,k,v,o,skip: K=2048, each N=1024 -> 40 n-tiles
    {
        Jobs J = {};
        J.K = Pp;
        J.X[0] = xc; J.W[0] = W_q;    J.bias[0] = b_q;     J.res[0] = nullptr;
        J.out[0] = q;  J.alpha[0] = 1.f;    J.N[0] = HDd;
        J.X[1] = xc; J.W[1] = W_k;    J.bias[1] = b_k;     J.res[1] = nullptr;
        J.out[1] = k;  J.alpha[1] = kscale; J.N[1] = HDd;
        J.X[2] = xt; J.W[2] = W_v;    J.bias[2] = b_v;     J.res[2] = nullptr;
        J.out[2] = v;  J.alpha[2] = 1.f;    J.N[2] = HDd;
        J.X[3] = xt; J.W[3] = W_o;    J.bias[3] = b_o;     J.res[3] = nullptr;
        J.out[3] = ol; J.alpha[3] = 1.f;    J.N[3] = HDd;
        J.X[4] = xc; J.W[4] = W_skip; J.bias[4] = nullptr; J.res[4] = nullptr;
        J.out[4] = sk; J.alpha[4] = 1.f;    J.N[4] = HDd;
        J.nt_start[0] = 0;  J.nt_start[1] = 8;  J.nt_start[2] = 16;
        J.nt_start[3] = 24; J.nt_start[4] = 32; J.nt_start[5] = 40;
        gemm_multi<<<dim3(2, 40), 256>>>(J);
    }

    gate_kernel<<<Bsz * Hn, 128>>>(c0, n0, m0, gn_g, gn_b, q, k, v, ol, sk, rt,
                                   it, ft, ct, nt, mt, z);

    // down-projection with residual add of seq
    {
        Jobs J = {};
        J.K = HDd;
        J.X[0] = z; J.W[0] = W_down; J.bias[0] = b_down; J.res[0] = seq;
        J.out[0] = outp; J.alpha[0] = 1.f; J.N[0] = Isz;
        J.nt_start[0] = 0; J.nt_start[1] = 8;
        J.nt_start[2] = 8; J.nt_start[3] = 8; J.nt_start[4] = 8; J.nt_start[5] = 8;
        gemm_multi<<<dim3(2, 8), 256>>>(J);
    }
}

// round 4
// speedup vs baseline: 5.7722x; 1.2807x over previous
#include <cuda_runtime.h>
#include <cstdint>
#include <cstddef>

#define Bsz 256
#define Isz 1024
#define Hn  8
#define Dd  128
#define Pp  2048
#define HDd 1024
#define EPSf 1e-5f

// ---------------- scratch (device global, no allocations) ----------------
#define OFF_XN   0u
#define OFF_XT   262144u
#define OFF_RT   786432u
#define OFF_XC   1048576u
#define OFF_Q    1572864u
#define OFF_K    1835008u
#define OFF_V    2097152u
#define OFF_OL   2359296u
#define OFF_SK   2621440u
#define OFF_Z    2883584u
#define OFF_WIF  3145728u   /* 128 x 2048 padded Wi/Wf */
#define OFF_BIF  3407872u   /* 128 padded bias */
#define OFF_ITFT 3408000u   /* 256 x 128 gate logits */
#define SCRATCH_FLOATS 3440768u
__device__ float g_scratch[SCRATCH_FLOATS];

// ---------------- helpers ----------------
__device__ __forceinline__ uint32_t f2tf32(float x) {
    uint32_t r;
    asm("cvt.rna.tf32.f32 %0, %1;" : "=r"(r) : "f"(x));
    return r;
}
__device__ __forceinline__ void mma_tf32(float c[4], const uint32_t a[4], const uint32_t b[2]) {
    asm volatile(
        "mma.sync.aligned.m16n8k8.row.col.f32.tf32.tf32.f32 "
        "{%0,%1,%2,%3},{%4,%5,%6,%7},{%8,%9},{%0,%1,%2,%3};"
        : "+f"(c[0]), "+f"(c[1]), "+f"(c[2]), "+f"(c[3])
        : "r"(a[0]), "r"(a[1]), "r"(a[2]), "r"(a[3]), "r"(b[0]), "r"(b[1]));
}
__device__ __forceinline__ float warp_sum(float v) {
    #pragma unroll
    for (int o = 16; o; o >>= 1) v += __shfl_xor_sync(0xffffffffu, v, o);
    return v;
}

// ---------------- LayerNorm over I=1024 ----------------
__global__ __launch_bounds__(256) void ln_kernel(
    const float* __restrict__ seq, const float* __restrict__ g,
    const float* __restrict__ bv, float* __restrict__ xn)
{
    __shared__ float red[16];
    int b = blockIdx.x, t = threadIdx.x;
    const float4* rowp = (const float4*)(seq + (size_t)b * Isz);
    float4 x = rowp[t];
    float s  = x.x + x.y + x.z + x.w;
    float s2 = x.x * x.x + x.y * x.y + x.z * x.z + x.w * x.w;
    s = warp_sum(s); s2 = warp_sum(s2);
    int lane = t & 31, w = t >> 5;
    if (lane == 0) { red[w] = s; red[8 + w] = s2; }
    __syncthreads();
    float su = 0.f, sq = 0.f;
    #pragma unroll
    for (int i = 0; i < 8; i++) { su += red[i]; sq += red[8 + i]; }
    float mu  = su * (1.f / 1024.f);
    float var = sq * (1.f / 1024.f) - mu * mu;
    float rs  = rsqrtf(var + EPSf);
    int c = t * 4;
    float4 o;
    o.x = (x.x - mu) * rs * g[c + 0] + bv[c + 0];
    o.y = (x.y - mu) * rs * g[c + 1] + bv[c + 1];
    o.z = (x.z - mu) * rs * g[c + 2] + bv[c + 2];
    o.w = (x.w - mu) * rs * g[c + 3] + bv[c + 3];
    ((float4*)(xn + (size_t)b * Isz))[t] = o;
}

// ---------------- causal conv (K=4 along feature axis) + SiLU ----------------
__global__ __launch_bounds__(256) void conv_kernel(
    const float* __restrict__ xt, const float* __restrict__ cw,
    const float* __restrict__ cb, float* __restrict__ xc)
{
    __shared__ float sr[Pp + 3];
    int b = blockIdx.x, t = threadIdx.x;
    for (int p = t; p < Pp; p += 256) sr[3 + p] = xt[(size_t)b * Pp + p];
    if (t < 3) sr[t] = 0.f;
    float w0 = cw[0], w1 = cw[1], w2 = cw[2], w3 = cw[3], cbv = cb[0];
    __syncthreads();
    for (int p = t; p < Pp; p += 256) {
        float a = cbv + w0 * sr[p] + w1 * sr[p + 1] + w2 * sr[p + 2] + w3 * sr[p + 3];
        xc[(size_t)b * Pp + p] = a / (1.f + expf(-a));
    }
}

// ---------------- pad Wi/Wf into 128x2048 block + packed bias ----------------
__global__ __launch_bounds__(256) void pad_if_kernel(
    const float* __restrict__ Wi, const float* __restrict__ Wf,
    const float* __restrict__ bi, const float* __restrict__ bfv,
    float* __restrict__ wif, float* __restrict__ bif)
{
    int r = blockIdx.x, t = threadIdx.x;
    const float* src = (r < 8) ? (Wi + (size_t)r * Pp)
                    : (r < 16) ? (Wf + (size_t)(r - 8) * Pp) : nullptr;
    float* dst = wif + (size_t)r * Pp;
    for (int c = t; c < Pp; c += 256) dst[c] = src ? src[c] : 0.f;
    if (r == 0 && t < 128)
        bif[t] = (t < 8) ? bi[t] : (t < 16) ? bfv[t - 8] : 0.f;
}

// ---------------- tf32 mma.sync batched GEMM ----------------
// BM=128, BN=64, BK=32. 256 threads = 8 warps, warp tile 32x32 (grid 4m x 2n).
// XOR-swizzled smem rows (32 floats = 8 quads; quad' = quad ^ (row&7)).
// Double-buffered smem, register-staged global prefetch. Exactly 48KB smem.
struct Jobs6 {
    const float* X[6];
    const float* W[6];
    const float* bias[6];
    const float* res[6];
    float* out[6];
    float alpha[6];
    int N[6];
    int nt_start[7];
    int K;
};

#define BM 128
#define BN 64
#define BK 32

__global__ __launch_bounds__(256, 2) void gemm_mma(Jobs6 J)
{
    __shared__ uint32_t As[2][BM * BK];
    __shared__ uint32_t Bs[2][BN * BK];

    int yt = blockIdx.y;
    int j = 0;
    while (yt >= J.nt_start[j + 1]) j++;
    const float* X = J.X[j];
    const float* W = J.W[j];
    int n0 = (yt - J.nt_start[j]) * BN;
    int m0 = blockIdx.x * BM;
    int K  = J.K;
    int S  = K / BK;

    int t = threadIdx.x, lane = t & 31, wid = t >> 5;
    int g = lane >> 2, qid = lane & 3;
    int wm = (wid & 3) * 32, wn = (wid >> 2) * 32;

    float acc[2][4][4];
    #pragma unroll
    for (int i = 0; i < 2; i++)
        #pragma unroll
        for (int jj = 0; jj < 4; jj++)
            #pragma unroll
            for (int l = 0; l < 4; l++) acc[i][jj][l] = 0.f;

    // STS geometry: A idx = t + i*256 (i<4): row=idx>>3, quad=idx&7
    //               B idx = t + i*256 (i<2)
    int aRow[4], aOff[4], bRow[2], bOff[2];
    #pragma unroll
    for (int i = 0; i < 4; i++) {
        int idx = t + i * 256;
        aRow[i] = idx >> 3;
        int qd = idx & 7;
        aOff[i] = aRow[i] * BK + ((qd ^ (aRow[i] & 7)) << 2);
    }
    #pragma unroll
    for (int i = 0; i < 2; i++) {
        int idx = t + i * 256;
        bRow[i] = idx >> 3;
        int qd = idx & 7;
        bOff[i] = bRow[i] * BK + ((qd ^ (bRow[i] & 7)) << 2);
    }

    float4 aR[4], bR[2];
    #define LDG_STAGE(kt)                                                        \
        do {                                                                     \
            _Pragma("unroll")                                                    \
            for (int i = 0; i < 4; i++)                                          \
                aR[i] = *(const float4*)(X + (size_t)(m0 + aRow[i]) * K + (kt)   \
                                         + ((t + i * 256) & 7) * 4);             \
            _Pragma("unroll")                                                    \
            for (int i = 0; i < 2; i++)                                          \
                bR[i] = *(const float4*)(W + (size_t)(n0 + bRow[i]) * K + (kt)   \
                                         + ((t + i * 256) & 7) * 4);             \
        } while (0)

    #define STS_STAGE(buf)                                                       \
        do {                                                                     \
            _Pragma("unroll")                                                    \
            for (int i = 0; i < 4; i++) {                                        \
                uint32_t* p = &As[buf][aOff[i]];                                 \
                p[0] = f2tf32(aR[i].x); p[1] = f2tf32(aR[i].y);                  \
                p[2] = f2tf32(aR[i].z); p[3] = f2tf32(aR[i].w);                  \
            }                                                                    \
            _Pragma("unroll")                                                    \
            for (int i = 0; i < 2; i++) {                                        \
                uint32_t* p = &Bs[buf][bOff[i]];                                 \
                p[0] = f2tf32(bR[i].x); p[1] = f2tf32(bR[i].y);                  \
                p[2] = f2tf32(bR[i].z); p[3] = f2tf32(bR[i].w);                  \
            }                                                                    \
        } while (0)

    #define COMPUTE_STAGE(buf)                                                   \
        do {                                                                     \
            _Pragma("unroll")                                                    \
            for (int ks = 0; ks < 4; ks++) {                                     \
                int q0 = (((2 * ks) ^ g) << 2) + qid;                            \
                int q1 = (((2 * ks + 1) ^ g) << 2) + qid;                        \
                uint32_t a[2][4], bb[4][2];                                      \
                _Pragma("unroll")                                                \
                for (int tm = 0; tm < 2; tm++) {                                 \
                    int r0 = (wm + tm * 16 + g) * BK;                            \
                    a[tm][0] = As[buf][r0 + q0];                                 \
                    a[tm][1] = As[buf][r0 + 8 * BK + q0];                        \
                    a[tm][2] = As[buf][r0 + q1];                                 \
                    a[tm][3] = As[buf][r0 + 8 * BK + q1];                        \
                }                                                                \
                _Pragma("unroll")                                                \
                for (int tn = 0; tn < 4; tn++) {                                 \
                    int rb = (wn + tn * 8 + g) * BK;                             \
                    bb[tn][0] = Bs[buf][rb + q0];                                \
                    bb[tn][1] = Bs[buf][rb + q1];                                \
                }                                                                \
                _Pragma("unroll")                                                \
                for (int tm = 0; tm < 2; tm++)                                   \
                    _Pragma("unroll")                                            \
                    for (int tn = 0; tn < 4; tn++)                               \
                        mma_tf32(acc[tm][tn], a[tm], bb[tn]);                    \
            }                                                                    \
        } while (0)

    LDG_STAGE(0);
    STS_STAGE(0);
    __syncthreads();

    for (int s = 0; s < S; s++) {
        if (s + 1 < S) LDG_STAGE((s + 1) * BK);
        COMPUTE_STAGE(s & 1);
        if (s + 1 < S) STS_STAGE((s + 1) & 1);
        __syncthreads();
    }

    // epilogue
    const float* bias = J.bias[j];
    const float* res  = J.res[j];
    float* out        = J.out[j];
    float alpha       = J.alpha[j];
    int N             = J.N[j];

    #pragma unroll
    for (int tm = 0; tm < 2; tm++) {
        #pragma unroll
        for (int half = 0; half < 2; half++) {
            int row = m0 + wm + tm * 16 + g + half * 8;
            #pragma unroll
            for (int tn = 0; tn < 4; tn++) {
                int col = n0 + wn + tn * 8 + qid * 2;
                float y0 = acc[tm][tn][half * 2 + 0];
                float y1 = acc[tm][tn][half * 2 + 1];
                if (bias) { y0 += bias[col]; y1 += bias[col + 1]; }
                y0 *= alpha; y1 *= alpha;
                if (res) {
                    y0 += res[(size_t)row * N + col];
                    y1 += res[(size_t)row * N + col + 1];
                }
                float2 yv; yv.x = y0; yv.y = y1;
                *(float2*)(out + (size_t)row * N + col) = yv;
            }
        }
    }
}

// ---------------- fused state update + gating + groupnorm + skip ----------------
__global__ __launch_bounds__(128) void gate_kernel(
    const float* __restrict__ c0, const float* __restrict__ n0,
    const float* __restrict__ m0, const float* __restrict__ gn_g,
    const float* __restrict__ gn_b,
    const float* __restrict__ q, const float* __restrict__ k,
    const float* __restrict__ v, const float* __restrict__ ol,
    const float* __restrict__ sk, const float* __restrict__ rt,
    const float* __restrict__ itft,
    float* __restrict__ ct_out, float* __restrict__ n_out,
    float* __restrict__ m_out, float* __restrict__ z_out)
{
    __shared__ float qs[128], ks[128], vs[128], nums[128], red[8];
    int bh = blockIdx.x;
    int b  = bh >> 3;
    int h  = bh & 7;
    int t = threadIdx.x, lane = t & 31, w = t >> 5;

    float itv = itft[b * 128 + h];
    float ftv = itft[b * 128 + 8 + h];
    float m0v = m0[bh];
    float mt = fmaxf(ftv + m0v, itv);
    float ie = expf(itv - mt);
    float fe = expf(ftv - mt + m0v);
    if (t == 0) m_out[bh] = mt;

    int base = bh * Dd;
    float qv = q[base + t], kv = k[base + t], vv = v[base + t];
    qs[t] = qv; ks[t] = kv; vs[t] = vv;

    float ntv = fe * n0[base + t] + ie * kv;
    n_out[base + t] = ntv;

    float dpart = warp_sum(ntv * qv);
    if (lane == 0) red[w] = dpart;
    __syncthreads();
    float den = fmaxf(1.0f, red[0] + red[1] + red[2] + red[3]);

    float4 kk = ((const float4*)ks)[lane];
    float4 qq = ((const float4*)qs)[lane];
    size_t crow_base = (size_t)bh * (Dd * Dd);
    for (int d = w; d < Dd; d += 4) {
        float vd = vs[d];
        float4 c0v = ((const float4*)(c0 + crow_base + (size_t)d * Dd))[lane];
        float4 ctv;
        float ivd = ie * vd;
        ctv.x = fe * c0v.x + ivd * kk.x;
        ctv.y = fe * c0v.y + ivd * kk.y;
        ctv.z = fe * c0v.z + ivd * kk.z;
        ctv.w = fe * c0v.w + ivd * kk.w;
        ((float4*)(ct_out + crow_base + (size_t)d * Dd))[lane] = ctv;
        float p = ctv.x * qq.x + ctv.y * qq.y + ctv.z * qq.z + ctv.w * qq.w;
        p = warp_sum(p);
        if (lane == 0) nums[d] = p;
    }
    __syncthreads();

    float numd = nums[t];
    float olv = ol[base + t];
    float osig = 1.f / (1.f + expf(-olv));
    float hd = osig * numd / den;

    float s1 = warp_sum(hd);
    float s2 = warp_sum(hd * hd);
    if (lane == 0) { red[w] = s1; red[4 + w] = s2; }
    __syncthreads();
    float mu  = (red[0] + red[1] + red[2] + red[3]) * (1.f / 128.f);
    float msq = (red[4] + red[5] + red[6] + red[7]) * (1.f / 128.f);
    float var = msq - mu * mu;
    float hn = (hd - mu) * rsqrtf(var + EPSf);

    float val = hn * gn_g[h * Dd + t] + gn_b[h * Dd + t] + sk[base + t];
    float rv = rt[base + t];
    val *= rv / (1.f + expf(-rv));
    z_out[base + t] = val;
}

// ---------------- launch ----------------
extern "C" void kernel_launch(void* const* d_in, const int* in_sizes, int n_in,
                              void* d_out, int out_size)
{
    const float* seq    = (const float*)d_in[0];
    const float* c0     = (const float*)d_in[1];
    const float* n0     = (const float*)d_in[2];
    const float* m0     = (const float*)d_in[3];
    const float* ln_g   = (const float*)d_in[4];
    const float* ln_b   = (const float*)d_in[5];
    const float* gn_g   = (const float*)d_in[6];
    const float* gn_b   = (const float*)d_in[7];
    const float* W_upl  = (const float*)d_in[8];
    const float* b_upl  = (const float*)d_in[9];
    const float* W_upr  = (const float*)d_in[10];
    const float* b_upr  = (const float*)d_in[11];
    const float* W_down = (const float*)d_in[12];
    const float* b_down = (const float*)d_in[13];
    const float* conv_w = (const float*)d_in[14];
    const float* conv_b = (const float*)d_in[15];
    const float* W_skip = (const float*)d_in[16];
    const float* W_i    = (const float*)d_in[17];
    const float* b_i    = (const float*)d_in[18];
    const float* W_f    = (const float*)d_in[19];
    const float* b_f    = (const float*)d_in[20];
    const float* W_o    = (const float*)d_in[21];
    const float* b_o    = (const float*)d_in[22];
    const float* W_q    = (const float*)d_in[23];
    const float* b_q    = (const float*)d_in[24];
    const float* W_k    = (const float*)d_in[25];
    const float* b_k    = (const float*)d_in[26];
    const float* W_v    = (const float*)d_in[27];
    const float* b_v    = (const float*)d_in[28];

    void* sp = nullptr;
    cudaGetSymbolAddress(&sp, g_scratch);
    float* S  = (float*)sp;
    float* xn   = S + OFF_XN;
    float* xt   = S + OFF_XT;
    float* rt   = S + OFF_RT;
    float* xc   = S + OFF_XC;
    float* q    = S + OFF_Q;
    float* k    = S + OFF_K;
    float* v    = S + OFF_V;
    float* ol   = S + OFF_OL;
    float* sk   = S + OFF_SK;
    float* z    = S + OFF_Z;
    float* wif  = S + OFF_WIF;
    float* bif  = S + OFF_BIF;
    float* itft = S + OFF_ITFT;

    float* outp = (float*)d_out;
    float* ct   = outp + (size_t)Bsz * Isz;
    float* nt   = ct + (size_t)Bsz * Hn * Dd * Dd;
    float* mt   = nt + (size_t)Bsz * Hn * Dd;

    const float kscale = 0.08838834764831845f;  // 1/sqrt(128)

    pad_if_kernel<<<128, 256>>>(W_i, W_f, b_i, b_f, wif, bif);
    ln_kernel<<<Bsz, 256>>>(seq, ln_g, ln_b, xn);

    // up-projections: [upl N=2048 -> 32 tiles][upr N=1024 -> 16 tiles], K=1024
    {
        Jobs6 J = {};
        J.K = Isz;
        J.X[0] = xn; J.W[0] = W_upl; J.bias[0] = b_upl; J.res[0] = nullptr;
        J.out[0] = xt; J.alpha[0] = 1.f; J.N[0] = Pp;
        J.X[1] = xn; J.W[1] = W_upr; J.bias[1] = b_upr; J.res[1] = nullptr;
        J.out[1] = rt; J.alpha[1] = 1.f; J.N[1] = HDd;
        J.nt_start[0] = 0; J.nt_start[1] = 32; J.nt_start[2] = 48;
        J.nt_start[3] = 48; J.nt_start[4] = 48; J.nt_start[5] = 48; J.nt_start[6] = 48;
        gemm_mma<<<dim3(2, 48), 256>>>(J);
    }

    conv_kernel<<<Bsz, 256>>>(xt, conv_w, conv_b, xc);

    // q,k,v,o,skip (16 tiles each) + if (2 tiles): K=2048 -> 82 n-tiles
    {
        Jobs6 J = {};
        J.K = Pp;
        J.X[0] = xc; J.W[0] = W_q;    J.bias[0] = b_q;     J.res[0] = nullptr;
        J.out[0] = q;    J.alpha[0] = 1.f;    J.N[0] = HDd;
        J.X[1] = xc; J.W[1] = W_k;    J.bias[1] = b_k;     J.res[1] = nullptr;
        J.out[1] = k;    J.alpha[1] = kscale; J.N[1] = HDd;
        J.X[2] = xt; J.W[2] = W_v;    J.bias[2] = b_v;     J.res[2] = nullptr;
        J.out[2] = v;    J.alpha[2] = 1.f;    J.N[2] = HDd;
        J.X[3] = xt; J.W[3] = W_o;    J.bias[3] = b_o;     J.res[3] = nullptr;
        J.out[3] = ol;   J.alpha[3] = 1.f;    J.N[3] = HDd;
        J.X[4] = xc; J.W[4] = W_skip; J.bias[4] = nullptr; J.res[4] = nullptr;
        J.out[4] = sk;   J.alpha[4] = 1.f;    J.N[4] = HDd;
        J.X[5] = xc; J.W[5] = wif;    J.bias[5] = bif;     J.res[5] = nullptr;
        J.out[5] = itft; J.alpha[5] = 1.f;    J.N[5] = 128;
        J.nt_start[0] = 0;  J.nt_start[1] = 16; J.nt_start[2] = 32;
        J.nt_start[3] = 48; J.nt_start[4] = 64; J.nt_start[5] = 80; J.nt_start[6] = 82;
        gemm_mma<<<dim3(2, 82), 256>>>(J);
    }

    gate_kernel<<<Bsz * Hn, 128>>>(c0, n0, m0, gn_g, gn_b, q, k, v, ol, sk, rt,
                                   itft, ct, nt, mt, z);

    // down-projection with residual add of seq: N=1024 -> 16 tiles, K=1024
    {
        Jobs6 J = {};
        J.K = HDd;
        J.X[0] = z; J.W[0] = W_down; J.bias[0] = b_down; J.res[0] = seq;
        J.out[0] = outp; J.alpha[0] = 1.f; J.N[0] = Isz;
        J.nt_start[0] = 0; J.nt_start[1] = 16;
        J.nt_start[2] = 16; J.nt_start[3] = 16; J.nt_start[4] = 16;
        J.nt_start[5] = 16; J.nt_start[6] = 16;
        gemm_mma<<<dim3(2, 16), 256>>>(J);
    }
}